// round 3
// baseline (speedup 1.0000x reference)
#include <cuda_runtime.h>
#include <cuda_fp16.h>
#include <math.h>

#define NN     32
#define TIN    12
#define HID    64
#define EPB    256
#define ET     288
#define E_     131072
#define NTH    256

// ---- shared memory map (float indices) ----
#define O_H1U   0        // half2/uint rows: 256 rows x 36 = 9216 (GAT1 features, fp16)
#define H1S     36       // uints per row (32 half2 + 4 pad)
#define O_H2    9216     // 32 x 68 fp32 = 2176
#define H2S     68
#define O_SRC   11392    // 288 int
#define O_DST   11680    // 288 int
#define O_CNT   11968    // 32 int
#define O_OFF   12000    // 33 int
#define O_SLOT  12033    // 288 int
#define O_CSR   12321    // 288 int -> 12609
#define O_X     12612    // 384 (dead after ph1)
#define O_ES    12996    // 256 (dead after ph3)
#define O_ED    13252    // 256 (dead after ph3)
#define O_E     13508    // 2304 fp32 p-values (dead after ph4)
// phase-6 scratch over dead X/ES/ED:
#define O_ES2   12612
#define O_ED2   12644
#define O_M2    12676
#define O_IS2   12708
#define O_E2    12740    // 288
#define O_AL2   13028    // 288 -> 13316
// phase-5 staging and G2 over dead E region:
#define O_SCR   13508    // 32 x 68 fp32 staging (phase 5)
#define SCRS    68
#define O_G2    13508    // 32 x 68 fp32 (phase 6-7)
#define G2S     68
// GRU phase (over dead H1/H2/ints/scratch):
#define O_HLNT  0        // 64 x 36 = 2304
#define HLS     36
#define O_XI    2304     // 64 x 192 = 12288 -> 14592
#define XIS     192
#define O_YS    14592    // 64 x 64 = 4096 -> 18688
#define YSS     64
#define O_HSM   18688    // 64
#define O_GH    18752    // 192 -> 18944
#define SMEM_FLOATS 18944   // 75776 B -> 3 CTAs/SM

__device__ __forceinline__ float sigmf_(float x){ return 1.0f/(1.0f+expf(-x)); }
__device__ __forceinline__ float eluf_(float x){ return x>0.f ? x : expm1f(x); }
__device__ __forceinline__ float lreluf_(float x){ return x>0.f ? x : 0.2f*x; }

__global__ void __launch_bounds__(NTH, 3) fused_gatgru_kernel(
    const float* __restrict__ x,   const int*   __restrict__ ei,
    const float* __restrict__ W1,  const float* __restrict__ aS1,
    const float* __restrict__ aD1, const float* __restrict__ b1,
    const float* __restrict__ W2,  const float* __restrict__ aS2,
    const float* __restrict__ aD2, const float* __restrict__ b2,
    const float* __restrict__ gamma, const float* __restrict__ beta,
    const float* __restrict__ Wi1, const float* __restrict__ Wh1,
    const float* __restrict__ bi1, const float* __restrict__ bh1,
    const float* __restrict__ Wi2, const float* __restrict__ Wh2,
    const float* __restrict__ bi2, const float* __restrict__ bh2,
    const float* __restrict__ Wf,  const float* __restrict__ bf,
    float* __restrict__ out)
{
    extern __shared__ float sm[];
    int*      smi  = (int*)sm;
    unsigned* smu  = (unsigned*)sm;
    __half2*  smh2 = (__half2*)sm;
    const int tid = threadIdx.x;
    const int b   = blockIdx.x;

    // ---------------- Phase 0: load x + edge list, zero counters
    {
        const float4* xg = (const float4*)(x + b*NN*TIN);
        float4* xs = (float4*)&sm[O_X];
        if (tid < 96) xs[tid] = xg[tid];
    }
    for (int k = tid; k < ET; k += NTH) {
        int s, d;
        if (k < EPB) { s = ei[b*EPB + k] - b*NN; d = ei[E_ + b*EPB + k] - b*NN; }
        else         { s = d = k - EPB; }
        smi[O_SRC + k] = s; smi[O_DST + k] = d;
    }
    if (tid < NN) smi[O_CNT + tid] = 0;
    __syncthreads();

    // ---------------- Phase 1: h1 = x @ W1 -> fp16 rows (n*8+h), + CSR counting
    {
        int h = tid >> 5, c2 = tid & 31;
        float w0[TIN], w1[TIN];
        #pragma unroll
        for (int k = 0; k < TIN; k++) {
            w0[k] = W1[k*512 + h*64 + 2*c2];
            w1[k] = W1[k*512 + h*64 + 2*c2 + 1];
        }
        for (int n = 0; n < NN; n++) {
            const float* xr = &sm[O_X + n*TIN];
            float a0 = 0.f, a1 = 0.f;
            #pragma unroll
            for (int k = 0; k < TIN; k++) {
                a0 = fmaf(xr[k], w0[k], a0);
                a1 = fmaf(xr[k], w1[k], a1);
            }
            smh2[(n*8 + h)*H1S + c2] = __floats2half2_rn(a0, a1);
        }
    }
    for (int k = tid; k < ET; k += NTH)
        smi[O_SLOT + k] = atomicAdd(&smi[O_CNT + smi[O_DST + k]], 1);
    __syncthreads();

    // ---------------- Phase 2: es/ed dots (fp16 rows) + CSR prefix sum
    {
        int n = tid >> 3, h = tid & 7;
        const uint4* hr = (const uint4*)&smu[(n*8 + h)*H1S];
        const float4* as = (const float4*)(aS1 + h*HID);
        const float4* ad = (const float4*)(aD1 + h*HID);
        float e0=0.f, e1=0.f, d0=0.f, d1=0.f;
        #pragma unroll
        for (int kk = 0; kk < 8; kk++) {
            uint4 u = hr[kk];
            float2 f0 = __half22float2(*(__half2*)&u.x);
            float2 f1 = __half22float2(*(__half2*)&u.y);
            float2 f2 = __half22float2(*(__half2*)&u.z);
            float2 f3 = __half22float2(*(__half2*)&u.w);
            float4 a0 = as[kk*2], a1 = as[kk*2+1];
            float4 g0 = ad[kk*2], g1 = ad[kk*2+1];
            e0 = fmaf(f0.x, a0.x, e0); e1 = fmaf(f0.y, a0.y, e1);
            e0 = fmaf(f1.x, a0.z, e0); e1 = fmaf(f1.y, a0.w, e1);
            e0 = fmaf(f2.x, a1.x, e0); e1 = fmaf(f2.y, a1.y, e1);
            e0 = fmaf(f3.x, a1.z, e0); e1 = fmaf(f3.y, a1.w, e1);
            d0 = fmaf(f0.x, g0.x, d0); d1 = fmaf(f0.y, g0.y, d1);
            d0 = fmaf(f1.x, g0.z, d0); d1 = fmaf(f1.y, g0.w, d1);
            d0 = fmaf(f2.x, g1.x, d0); d1 = fmaf(f2.y, g1.y, d1);
            d0 = fmaf(f3.x, g1.z, d0); d1 = fmaf(f3.y, g1.w, d1);
        }
        sm[O_ES + n*8 + h] = e0 + e1;
        sm[O_ED + n*8 + h] = d0 + d1;
    }
    if (tid == 0) {
        int acc = 0;
        for (int d = 0; d < NN; d++) { smi[O_OFF + d] = acc; acc += smi[O_CNT + d]; }
        smi[O_OFF + NN] = acc;
    }
    __syncthreads();

    // ---------------- Phase 3: edge scores + CSR scatter
    for (int k = tid; k < ET; k += NTH) {
        int s = smi[O_SRC + k], d = smi[O_DST + k];
        const float4* es = (const float4*)&sm[O_ES + s*8];
        const float4* ed = (const float4*)&sm[O_ED + d*8];
        float4* eo = (float4*)&sm[O_E + k*8];
        float4 a0 = es[0], a1 = es[1], b0 = ed[0], b1 = ed[1];
        float4 r0, r1;
        r0.x = lreluf_(a0.x + b0.x); r0.y = lreluf_(a0.y + b0.y);
        r0.z = lreluf_(a0.z + b0.z); r0.w = lreluf_(a0.w + b0.w);
        r1.x = lreluf_(a1.x + b1.x); r1.y = lreluf_(a1.y + b1.y);
        r1.z = lreluf_(a1.z + b1.z); r1.w = lreluf_(a1.w + b1.w);
        eo[0] = r0; eo[1] = r1;
    }
    for (int k = tid; k < ET; k += NTH)
        smi[O_CSR + smi[O_OFF + smi[O_DST + k]] + smi[O_SLOT + k]] = k;
    __syncthreads();

    // ---------------- Phase 4: GAT1 softmax + aggregation, 2 channel-passes (32 ch each)
    {
        int dst = tid >> 3, h = tid & 7;
        int o   = smi[O_OFF + dst], deg = smi[O_OFF + dst + 1] - o;
        float m = -1e30f;
        for (int i = 0; i < deg; i++)
            m = fmaxf(m, sm[O_E + smi[O_CSR + o + i]*8 + h]);
        float s = 0.f;
        for (int i = 0; i < deg; i++) {
            int k = smi[O_CSR + o + i];
            float p = expf(sm[O_E + k*8 + h] - m);
            sm[O_E + k*8 + h] = p;
            s += p;
        }
        float inv = 1.f/(s + 1e-16f);
        for (int hh = 0; hh < 2; hh++) {
            float acc[32];
            #pragma unroll
            for (int c = 0; c < 32; c++) acc[c] = 0.f;
            for (int i = 0; i < deg; i++) {
                int k = smi[O_CSR + o + i];
                float p = sm[O_E + k*8 + h];
                const uint4* rp = (const uint4*)&smu[(smi[O_SRC + k]*8 + h)*H1S + hh*16];
                #pragma unroll
                for (int q = 0; q < 4; q++) {
                    uint4 u = rp[q];
                    float2 f0 = __half22float2(*(__half2*)&u.x);
                    float2 f1 = __half22float2(*(__half2*)&u.y);
                    float2 f2 = __half22float2(*(__half2*)&u.z);
                    float2 f3 = __half22float2(*(__half2*)&u.w);
                    acc[q*8+0] = fmaf(p, f0.x, acc[q*8+0]);
                    acc[q*8+1] = fmaf(p, f0.y, acc[q*8+1]);
                    acc[q*8+2] = fmaf(p, f1.x, acc[q*8+2]);
                    acc[q*8+3] = fmaf(p, f1.y, acc[q*8+3]);
                    acc[q*8+4] = fmaf(p, f2.x, acc[q*8+4]);
                    acc[q*8+5] = fmaf(p, f2.y, acc[q*8+5]);
                    acc[q*8+6] = fmaf(p, f3.x, acc[q*8+6]);
                    acc[q*8+7] = fmaf(p, f3.y, acc[q*8+7]);
                }
            }
            __syncthreads();   // all reads of this channel range complete
            {
                const float* bp = b1 + h*HID + hh*32;
                __half2* wp = &smh2[(dst*8 + h)*H1S + hh*16];
                #pragma unroll
                for (int q = 0; q < 16; q++) {
                    float v0 = eluf_(fmaf(acc[q*2+0], inv, bp[q*2+0]));
                    float v1 = eluf_(fmaf(acc[q*2+1], inv, bp[q*2+1]));
                    wp[q] = __floats2half2_rn(v0, v1);
                }
            }
            __syncthreads();
        }
    }

    // ---------------- Phase 5: h2 = out1 @ W2, per-head fp32 staging
    {
        int c = tid & 63, grp = tid >> 6;
        float acc[8];
        #pragma unroll
        for (int i = 0; i < 8; i++) acc[i] = 0.f;
        for (int hd = 0; hd < 8; hd++) {
            // stage head slice (32 x 64) to fp32
            #pragma unroll
            for (int it = 0; it < 4; it++) {
                int idx = tid + it*NTH;         // 0..1023
                int n = idx >> 5, c2 = idx & 31;
                float2 f = __half22float2(smh2[(n*8 + hd)*H1S + c2]);
                *(float2*)&sm[O_SCR + n*SCRS + 2*c2] = f;
            }
            __syncthreads();
            const float* w2p = W2 + hd*64*HID + c;
            #pragma unroll 4
            for (int kc = 0; kc < 64; kc += 4) {
                float w0 = w2p[(kc+0)*HID], w1 = w2p[(kc+1)*HID];
                float w2v = w2p[(kc+2)*HID], w3 = w2p[(kc+3)*HID];
                #pragma unroll
                for (int i = 0; i < 8; i++) {
                    float4 v = *(const float4*)&sm[O_SCR + (grp*8+i)*SCRS + kc];
                    float t0 = fmaf(v.x, w0, v.y*w1);
                    float t1 = fmaf(v.z, w2v, v.w*w3);
                    acc[i] += t0 + t1;
                }
            }
            __syncthreads();
        }
        #pragma unroll
        for (int i = 0; i < 8; i++) sm[O_H2 + (grp*8+i)*H2S + c] = acc[i];
    }
    __syncthreads();

    // ---------------- Phase 6: GAT2 attention
    if (tid < 64) {
        int n = tid & 31;
        const float4* a  = (const float4*)((tid < 32) ? aS2 : aD2);
        const float4* hr = (const float4*)&sm[O_H2 + n*H2S];
        float a0 = 0.f, a1 = 0.f;
        #pragma unroll
        for (int kk = 0; kk < 16; kk++) {
            float4 v = hr[kk], w = a[kk];
            a0 = fmaf(v.x, w.x, a0); a1 = fmaf(v.y, w.y, a1);
            a0 = fmaf(v.z, w.z, a0); a1 = fmaf(v.w, w.w, a1);
        }
        sm[(tid < 32 ? O_ES2 : O_ED2) + n] = a0 + a1;
    }
    __syncthreads();
    for (int k = tid; k < ET; k += NTH)
        sm[O_E2 + k] = lreluf_(sm[O_ES2 + smi[O_SRC + k]] + sm[O_ED2 + smi[O_DST + k]]);
    __syncthreads();
    if (tid < NN) {
        int o = smi[O_OFF + tid], deg = smi[O_OFF + tid + 1] - o;
        float m = -1e30f;
        for (int i = 0; i < deg; i++) m = fmaxf(m, sm[O_E2 + smi[O_CSR + o + i]]);
        float s = 0.f;
        for (int i = 0; i < deg; i++) s += expf(sm[O_E2 + smi[O_CSR + o + i]] - m);
        sm[O_M2 + tid]  = m;
        sm[O_IS2 + tid] = 1.f/(s + 1e-16f);
    }
    __syncthreads();
    for (int k = tid; k < ET; k += NTH) {
        int d = smi[O_DST + k];
        sm[O_AL2 + k] = expf(sm[O_E2 + k] - sm[O_M2 + d]) * sm[O_IS2 + d];
    }
    __syncthreads();
    {
        int dst = tid >> 3, cc = (tid & 7) * 8;
        int o = smi[O_OFF + dst], deg = smi[O_OFF + dst + 1] - o;
        float4 a0 = make_float4(0.f,0.f,0.f,0.f), a1 = a0;
        for (int i = 0; i < deg; i++) {
            int k = smi[O_CSR + o + i];
            float al = sm[O_AL2 + k];
            const float4* hr = (const float4*)&sm[O_H2 + smi[O_SRC + k]*H2S + cc];
            float4 v0 = hr[0], v1 = hr[1];
            a0.x = fmaf(al, v0.x, a0.x); a0.y = fmaf(al, v0.y, a0.y);
            a0.z = fmaf(al, v0.z, a0.z); a0.w = fmaf(al, v0.w, a0.w);
            a1.x = fmaf(al, v1.x, a1.x); a1.y = fmaf(al, v1.y, a1.y);
            a1.z = fmaf(al, v1.z, a1.z); a1.w = fmaf(al, v1.w, a1.w);
        }
        const float4* bb = (const float4*)(b2 + cc);
        float4 b0 = bb[0], b1v = bb[1], r0, r1;
        r0.x = eluf_(a0.x + b0.x); r0.y = eluf_(a0.y + b0.y);
        r0.z = eluf_(a0.z + b0.z); r0.w = eluf_(a0.w + b0.w);
        r1.x = eluf_(a1.x + b1v.x); r1.y = eluf_(a1.y + b1v.y);
        r1.z = eluf_(a1.z + b1v.z); r1.w = eluf_(a1.w + b1v.w);
        float4* g = (float4*)&sm[O_G2 + dst*G2S + cc];
        g[0] = r0; g[1] = r1;
    }
    __syncthreads();

    // ---------------- Phase 7: LayerNorm -> hlnT[t][n] (stride 36)
    if (tid < NN) {
        const float4* r4 = (const float4*)&sm[O_G2 + tid*G2S];
        float4 row[16];
        float mu = 0.f;
        #pragma unroll
        for (int kk = 0; kk < 16; kk++) {
            row[kk] = r4[kk];
            mu += (row[kk].x + row[kk].y) + (row[kk].z + row[kk].w);
        }
        mu *= (1.f/HID);
        float var = 0.f;
        #pragma unroll
        for (int kk = 0; kk < 16; kk++) {
            float dx = row[kk].x-mu, dy = row[kk].y-mu, dz = row[kk].z-mu, dw = row[kk].w-mu;
            var += fmaf(dx,dx, dy*dy) + fmaf(dz,dz, dw*dw);
        }
        var *= (1.f/HID);
        float is = rsqrtf(var + 1e-5f);
        #pragma unroll
        for (int kk = 0; kk < 16; kk++) {
            int t = kk*4;
            sm[O_HLNT + (t+0)*HLS + tid] = (row[kk].x - mu)*is*gamma[t+0] + beta[t+0];
            sm[O_HLNT + (t+1)*HLS + tid] = (row[kk].y - mu)*is*gamma[t+1] + beta[t+1];
            sm[O_HLNT + (t+2)*HLS + tid] = (row[kk].z - mu)*is*gamma[t+2] + beta[t+2];
            sm[O_HLNT + (t+3)*HLS + tid] = (row[kk].w - mu)*is*gamma[t+3] + beta[t+3];
        }
    }
    __syncthreads();

    // ---------------- Phase 8: xi1[t][j] = bi1[j] + Wi1[j] . hlnT[t]
    for (int o = tid; o < 64*192; o += NTH) {
        int t = o / 192, j = o - t*192;
        const float4* wr = (const float4*)(Wi1 + j*NN);
        const float4* hr = (const float4*)&sm[O_HLNT + t*HLS];
        float a0=0.f, a1=0.f, a2=0.f, a3=0.f;
        #pragma unroll
        for (int kk = 0; kk < 8; kk++) {
            float4 w = wr[kk], v = hr[kk];
            a0 = fmaf(w.x, v.x, a0); a1 = fmaf(w.y, v.y, a1);
            a2 = fmaf(w.z, v.z, a2); a3 = fmaf(w.w, v.w, a3);
        }
        sm[O_XI + t*XIS + j] = bi1[j] + ((a0+a1) + (a2+a3));
    }
    // Wh1 rows into registers
    float4 wh4[16]; float bh = 0.f;
    if (tid < 192) {
        bh = bh1[tid];
        const float4* w = (const float4*)(Wh1 + tid*HID);
        #pragma unroll
        for (int kk = 0; kk < 16; kk++) wh4[kk] = w[kk];
    }
    if (tid < HID) sm[O_HSM + tid] = 0.f;
    __syncthreads();

    // ---------------- Phase 9: GRU1 recurrence (64 steps), store ys
    for (int t = 0; t < HID; t++) {
        if (tid < 192) {
            const float4* h4 = (const float4*)&sm[O_HSM];
            float a0 = bh, a1 = 0.f, a2 = 0.f, a3 = 0.f;
            #pragma unroll
            for (int kk = 0; kk < 16; kk++) {
                float4 hv = h4[kk];
                a0 = fmaf(wh4[kk].x, hv.x, a0); a1 = fmaf(wh4[kk].y, hv.y, a1);
                a2 = fmaf(wh4[kk].z, hv.z, a2); a3 = fmaf(wh4[kk].w, hv.w, a3);
            }
            sm[O_GH + tid] = (a0+a1) + (a2+a3);
        }
        __syncthreads();
        if (tid < HID) {
            const float* xr = &sm[O_XI + t*XIS];
            float r  = sigmf_(xr[tid]       + sm[O_GH + tid]);
            float z  = sigmf_(xr[64 + tid]  + sm[O_GH + 64 + tid]);
            float nv = tanhf(fmaf(r, sm[O_GH + 128 + tid], xr[128 + tid]));
            float hn = (1.f - z)*nv + z*sm[O_HSM + tid];
            sm[O_HSM + tid]        = hn;
            sm[O_YS + t*YSS + tid] = hn;
        }
        __syncthreads();
    }

    // ---------------- Phase 10: xi2[t][j] = bi2[j] + Wi2[j] . ys[t]
    for (int o = tid; o < 64*192; o += NTH) {
        int t = o / 192, j = o - t*192;
        const float4* wr = (const float4*)(Wi2 + j*HID);
        const float4* yr = (const float4*)&sm[O_YS + t*YSS];
        float a0=0.f, a1=0.f, a2=0.f, a3=0.f;
        #pragma unroll
        for (int kk = 0; kk < 16; kk++) {
            float4 w = wr[kk], v = yr[kk];
            a0 = fmaf(w.x, v.x, a0); a1 = fmaf(w.y, v.y, a1);
            a2 = fmaf(w.z, v.z, a2); a3 = fmaf(w.w, v.w, a3);
        }
        sm[O_XI + t*XIS + j] = bi2[j] + ((a0+a1) + (a2+a3));
    }
    if (tid < 192) {
        bh = bh2[tid];
        const float4* w = (const float4*)(Wh2 + tid*HID);
        #pragma unroll
        for (int kk = 0; kk < 16; kk++) wh4[kk] = w[kk];
    }
    if (tid < HID) sm[O_HSM + tid] = 0.f;
    __syncthreads();

    // ---------------- Phase 11: GRU2 recurrence (final h only)
    for (int t = 0; t < HID; t++) {
        if (tid < 192) {
            const float4* h4 = (const float4*)&sm[O_HSM];
            float a0 = bh, a1 = 0.f, a2 = 0.f, a3 = 0.f;
            #pragma unroll
            for (int kk = 0; kk < 16; kk++) {
                float4 hv = h4[kk];
                a0 = fmaf(wh4[kk].x, hv.x, a0); a1 = fmaf(wh4[kk].y, hv.y, a1);
                a2 = fmaf(wh4[kk].z, hv.z, a2); a3 = fmaf(wh4[kk].w, hv.w, a3);
            }
            sm[O_GH + tid] = (a0+a1) + (a2+a3);
        }
        __syncthreads();
        if (tid < HID) {
            const float* xr = &sm[O_XI + t*XIS];
            float r  = sigmf_(xr[tid]       + sm[O_GH + tid]);
            float z  = sigmf_(xr[64 + tid]  + sm[O_GH + 64 + tid]);
            float nv = tanhf(fmaf(r, sm[O_GH + 128 + tid], xr[128 + tid]));
            sm[O_HSM + tid] = (1.f - z)*nv + z*sm[O_HSM + tid];
        }
        __syncthreads();
    }

    // ---------------- Phase 12: final linear
    if (tid < 9) {
        const float4* w = (const float4*)(Wf + tid*HID);
        const float4* h4 = (const float4*)&sm[O_HSM];
        float a0 = bf[tid], a1 = 0.f, a2 = 0.f, a3 = 0.f;
        #pragma unroll
        for (int kk = 0; kk < 16; kk++) {
            float4 wv = w[kk], hv = h4[kk];
            a0 = fmaf(wv.x, hv.x, a0); a1 = fmaf(wv.y, hv.y, a1);
            a2 = fmaf(wv.z, hv.z, a2); a3 = fmaf(wv.w, hv.w, a3);
        }
        out[b*9 + tid] = (a0+a1) + (a2+a3);
    }
}

extern "C" void kernel_launch(void* const* d_in, const int* in_sizes, int n_in,
                              void* d_out, int out_size) {
    (void)in_sizes; (void)n_in; (void)out_size;
    const float* x    = (const float*)d_in[0];
    const int*   ei   = (const int*)  d_in[1];
    const float* W1   = (const float*)d_in[2];
    const float* aS1  = (const float*)d_in[3];
    const float* aD1  = (const float*)d_in[4];
    const float* b1   = (const float*)d_in[5];
    const float* W2   = (const float*)d_in[6];
    const float* aS2  = (const float*)d_in[7];
    const float* aD2  = (const float*)d_in[8];
    const float* b2   = (const float*)d_in[9];
    const float* gam  = (const float*)d_in[10];
    const float* bet  = (const float*)d_in[11];
    const float* Wi1  = (const float*)d_in[12];
    const float* Wh1  = (const float*)d_in[13];
    const float* bi1  = (const float*)d_in[14];
    const float* bh1  = (const float*)d_in[15];
    const float* Wi2  = (const float*)d_in[16];
    const float* Wh2  = (const float*)d_in[17];
    const float* bi2  = (const float*)d_in[18];
    const float* bh2  = (const float*)d_in[19];
    const float* Wf   = (const float*)d_in[20];
    const float* bf   = (const float*)d_in[21];
    float* out = (float*)d_out;

    size_t smem = (size_t)SMEM_FLOATS * sizeof(float);
    cudaFuncSetAttribute(fused_gatgru_kernel,
                         cudaFuncAttributeMaxDynamicSharedMemorySize, (int)smem);
    fused_gatgru_kernel<<<512, NTH, smem>>>(
        x, ei, W1, aS1, aD1, b1, W2, aS2, aD2, b2, gam, bet,
        Wi1, Wh1, bi1, bh1, Wi2, Wh2, bi2, bh2, Wf, bf, out);
}

// round 4
// speedup vs baseline: 2.9478x; 2.9478x over previous
#include <cuda_runtime.h>
#include <math.h>

#define NN     32
#define TIN    12
#define HID    64
#define HEADS  8
#define HH     512
#define EPB    256
#define ET     288
#define E_     131072
#define NTH    256
#define RS     68
#define H2S    68
#define HLNTS  36
#define XIS    196
#define YSS    68

// shared memory offsets (floats) — same map as the 414us kernel
#define O_H1    0
#define O_XI    0
#define O_YS    12544
#define O_X     17408
#define O_ES2   17408
#define O_ED2   17440
#define O_M2    17472
#define O_IS2   17504
#define O_AL2   17536
#define O_ES    17792
#define O_E2    17824
#define O_ED    18048
#define O_E     18304
#define O_HLNT  18304
#define O_SRC   20608
#define O_DST   20896
#define O_CNT   21184
#define O_OFF   21216
#define O_SLOT  21249
#define O_CSR   21537
#define O_H2    21828
#define O_G2    24004
#define O_HSM   24004
#define O_GH    24068
#define SMEM_FLOATS 26180

typedef unsigned long long u64t;

__device__ __forceinline__ u64t pk2(float lo, float hi) {
    u64t r; asm("mov.b64 %0, {%1, %2};" : "=l"(r) : "f"(lo), "f"(hi)); return r;
}
__device__ __forceinline__ void fma2(u64t& d, u64t a, u64t b) {
    asm("fma.rn.f32x2 %0, %1, %2, %3;" : "=l"(d) : "l"(a), "l"(b), "l"(d));
}
__device__ __forceinline__ float2 up2(u64t v) {
    float2 f; asm("mov.b64 {%0, %1}, %2;" : "=f"(f.x), "=f"(f.y) : "l"(v)); return f;
}
__device__ __forceinline__ float red2(u64t a, u64t b) {
    float2 fa = up2(a), fb = up2(b);
    return (fa.x + fa.y) + (fb.x + fb.y);
}

__device__ __forceinline__ float sigmf_(float x){ return __fdividef(1.0f, 1.0f + __expf(-x)); }
__device__ __forceinline__ float tanhf_(float x){ return 1.0f - __fdividef(2.0f, __expf(2.0f*x) + 1.0f); }
__device__ __forceinline__ float eluf_(float x){ return x>0.f ? x : (__expf(x) - 1.0f); }
__device__ __forceinline__ float lreluf_(float x){ return x>0.f ? x : 0.2f*x; }

__global__ void __launch_bounds__(NTH, 2) fused_gatgru_kernel(
    const float* __restrict__ x,   const int*   __restrict__ ei,
    const float* __restrict__ W1,  const float* __restrict__ aS1,
    const float* __restrict__ aD1, const float* __restrict__ b1,
    const float* __restrict__ W2,  const float* __restrict__ aS2,
    const float* __restrict__ aD2, const float* __restrict__ b2,
    const float* __restrict__ gamma, const float* __restrict__ beta,
    const float* __restrict__ Wi1, const float* __restrict__ Wh1,
    const float* __restrict__ bi1, const float* __restrict__ bh1,
    const float* __restrict__ Wi2, const float* __restrict__ Wh2,
    const float* __restrict__ bi2, const float* __restrict__ bh2,
    const float* __restrict__ Wf,  const float* __restrict__ bf,
    float* __restrict__ out)
{
    extern __shared__ float sm[];
    int* smi = (int*)sm;
    const int tid = threadIdx.x;
    const int b   = blockIdx.x;

    // ---------------- Phase 0
    {
        const float4* xg = (const float4*)(x + b*NN*TIN);
        float4* xs = (float4*)&sm[O_X];
        if (tid < 96) xs[tid] = xg[tid];
    }
    for (int k = tid; k < ET; k += NTH) {
        int s, d;
        if (k < EPB) { s = ei[b*EPB + k] - b*NN; d = ei[E_ + b*EPB + k] - b*NN; }
        else         { s = d = k - EPB; }
        smi[O_SRC + k] = s; smi[O_DST + k] = d;
    }
    if (tid < NN) smi[O_CNT + tid] = 0;
    __syncthreads();

    // ---------------- Phase 1: h1 = x @ W1 (packed f32x2 over k)
    for (int jj = 0; jj < 2; jj++) {
        int j = tid + jj*NTH;
        int h = j >> 6, c = j & 63;
        u64t wp[6];
        #pragma unroll
        for (int k = 0; k < 6; k++)
            wp[k] = pk2(W1[(2*k)*HH + j], W1[(2*k+1)*HH + j]);
        for (int n = 0; n < NN; n++) {
            const float4* xr = (const float4*)&sm[O_X + n*TIN];
            float4 x0 = xr[0], x1 = xr[1], x2 = xr[2];
            u64t a0 = 0ull, a1 = 0ull;
            fma2(a0, pk2(x0.x,x0.y), wp[0]);
            fma2(a1, pk2(x0.z,x0.w), wp[1]);
            fma2(a0, pk2(x1.x,x1.y), wp[2]);
            fma2(a1, pk2(x1.z,x1.w), wp[3]);
            fma2(a0, pk2(x2.x,x2.y), wp[4]);
            fma2(a1, pk2(x2.z,x2.w), wp[5]);
            sm[O_H1 + (n*8 + h)*RS + c] = red2(a0, a1);
        }
    }
    for (int k = tid; k < ET; k += NTH)
        smi[O_SLOT + k] = atomicAdd(&smi[O_CNT + smi[O_DST + k]], 1);
    __syncthreads();

    // ---------------- Phase 2: es/ed dots (packed) + prefix sum
    {
        int n = tid >> 3, h = tid & 7;
        const float4* hr = (const float4*)&sm[O_H1 + (n*8 + h)*RS];
        const float4* as = (const float4*)(aS1 + h*HID);
        const float4* ad = (const float4*)(aD1 + h*HID);
        u64t e0 = 0ull, e1 = 0ull, d0 = 0ull, d1 = 0ull;
        #pragma unroll
        for (int kk = 0; kk < 16; kk++) {
            float4 v = hr[kk], a = as[kk], g = ad[kk];
            u64t vxy = pk2(v.x, v.y), vzw = pk2(v.z, v.w);
            fma2(e0, vxy, pk2(a.x, a.y));
            fma2(e1, vzw, pk2(a.z, a.w));
            fma2(d0, vxy, pk2(g.x, g.y));
            fma2(d1, vzw, pk2(g.z, g.w));
        }
        sm[O_ES + n*8 + h] = red2(e0, e1);
        sm[O_ED + n*8 + h] = red2(d0, d1);
    }
    if (tid == 0) {
        int acc = 0;
        for (int d = 0; d < NN; d++) { smi[O_OFF + d] = acc; acc += smi[O_CNT + d]; }
        smi[O_OFF + NN] = acc;
    }
    __syncthreads();

    // ---------------- Phase 3: edge scores + CSR scatter
    for (int k = tid; k < ET; k += NTH) {
        int s = smi[O_SRC + k], d = smi[O_DST + k];
        const float4* es = (const float4*)&sm[O_ES + s*8];
        const float4* ed = (const float4*)&sm[O_ED + d*8];
        float4* eo = (float4*)&sm[O_E + k*8];
        float4 a0 = es[0], a1 = es[1], b0 = ed[0], b1 = ed[1];
        float4 r0, r1;
        r0.x = lreluf_(a0.x + b0.x); r0.y = lreluf_(a0.y + b0.y);
        r0.z = lreluf_(a0.z + b0.z); r0.w = lreluf_(a0.w + b0.w);
        r1.x = lreluf_(a1.x + b1.x); r1.y = lreluf_(a1.y + b1.y);
        r1.z = lreluf_(a1.z + b1.z); r1.w = lreluf_(a1.w + b1.w);
        eo[0] = r0; eo[1] = r1;
    }
    for (int k = tid; k < ET; k += NTH)
        smi[O_CSR + smi[O_OFF + smi[O_DST + k]] + smi[O_SLOT + k]] = k;
    __syncthreads();

    // ---------------- Phase 4: GAT1 softmax + aggregation (packed accumulate)
    {
        int dst = tid >> 3, h = tid & 7;
        int o   = smi[O_OFF + dst], deg = smi[O_OFF + dst + 1] - o;
        float m = -1e30f;
        for (int i = 0; i < deg; i++)
            m = fmaxf(m, sm[O_E + smi[O_CSR + o + i]*8 + h]);
        float s = 0.f;
        for (int i = 0; i < deg; i++) {
            int k = smi[O_CSR + o + i];
            float p = __expf(sm[O_E + k*8 + h] - m);
            sm[O_E + k*8 + h] = p;
            s += p;
        }
        float inv = __fdividef(1.f, s + 1e-16f);
        u64t acc[32];
        #pragma unroll
        for (int j = 0; j < 32; j++) acc[j] = 0ull;
        for (int i = 0; i < deg; i++) {
            int k = smi[O_CSR + o + i];
            float p = sm[O_E + k*8 + h];
            u64t pp = pk2(p, p);
            const float4* hr = (const float4*)&sm[O_H1 + (smi[O_SRC + k]*8 + h)*RS];
            #pragma unroll
            for (int j = 0; j < 16; j++) {
                float4 v = hr[j];
                fma2(acc[2*j],   pp, pk2(v.x, v.y));
                fma2(acc[2*j+1], pp, pk2(v.z, v.w));
            }
        }
        __syncthreads();   // all h1 reads complete before in-place overwrite
        float4* orow = (float4*)&sm[O_H1 + (dst*8 + h)*RS];
        const float4* bb = (const float4*)(b1 + h*HID);
        #pragma unroll
        for (int j = 0; j < 16; j++) {
            float4 bv = bb[j], r;
            float2 lo = up2(acc[2*j]), hi = up2(acc[2*j+1]);
            r.x = eluf_(fmaf(lo.x, inv, bv.x));
            r.y = eluf_(fmaf(lo.y, inv, bv.y));
            r.z = eluf_(fmaf(hi.x, inv, bv.z));
            r.w = eluf_(fmaf(hi.y, inv, bv.w));
            orow[j] = r;
        }
    }
    __syncthreads();

    // ---------------- Phase 5: h2 = out1 @ W2 (packed over k)
    {
        int c = tid & 63, grp = tid >> 6;
        u64t accA[8], accB[8];
        #pragma unroll
        for (int i = 0; i < 8; i++) { accA[i] = 0ull; accB[i] = 0ull; }
        for (int hd = 0; hd < 8; hd++) {
            const float* w2p = W2 + hd*64*HID + c;
            #pragma unroll 4
            for (int kc = 0; kc < 64; kc += 4) {
                u64t wA = pk2(w2p[(kc+0)*HID], w2p[(kc+1)*HID]);
                u64t wB = pk2(w2p[(kc+2)*HID], w2p[(kc+3)*HID]);
                #pragma unroll
                for (int i = 0; i < 8; i++) {
                    float4 v = *(const float4*)&sm[O_H1 + ((grp*8+i)*8 + hd)*RS + kc];
                    fma2(accA[i], pk2(v.x, v.y), wA);
                    fma2(accB[i], pk2(v.z, v.w), wB);
                }
            }
        }
        #pragma unroll
        for (int i = 0; i < 8; i++)
            sm[O_H2 + (grp*8+i)*H2S + c] = red2(accA[i], accB[i]);
    }
    __syncthreads();

    // ---------------- Phase 6: GAT2 attention
    if (tid < 64) {
        int n = tid & 31;
        const float4* a  = (const float4*)((tid < 32) ? aS2 : aD2);
        const float4* hr = (const float4*)&sm[O_H2 + n*H2S];
        u64t a0 = 0ull, a1 = 0ull;
        #pragma unroll
        for (int kk = 0; kk < 16; kk++) {
            float4 v = hr[kk], w = a[kk];
            fma2(a0, pk2(v.x, v.y), pk2(w.x, w.y));
            fma2(a1, pk2(v.z, v.w), pk2(w.z, w.w));
        }
        sm[(tid < 32 ? O_ES2 : O_ED2) + n] = red2(a0, a1);
    }
    __syncthreads();
    for (int k = tid; k < ET; k += NTH)
        sm[O_E2 + k] = lreluf_(sm[O_ES2 + smi[O_SRC + k]] + sm[O_ED2 + smi[O_DST + k]]);
    __syncthreads();
    if (tid < NN) {
        int o = smi[O_OFF + tid], deg = smi[O_OFF + tid + 1] - o;
        float m = -1e30f;
        for (int i = 0; i < deg; i++) m = fmaxf(m, sm[O_E2 + smi[O_CSR + o + i]]);
        float s = 0.f;
        for (int i = 0; i < deg; i++) s += __expf(sm[O_E2 + smi[O_CSR + o + i]] - m);
        sm[O_M2 + tid]  = m;
        sm[O_IS2 + tid] = __fdividef(1.f, s + 1e-16f);
    }
    __syncthreads();
    for (int k = tid; k < ET; k += NTH) {
        int d = smi[O_DST + k];
        sm[O_AL2 + k] = __expf(sm[O_E2 + k] - sm[O_M2 + d]) * sm[O_IS2 + d];
    }
    __syncthreads();
    {   // aggregation + bias + elu -> g2
        int dst = tid >> 3, cc = (tid & 7) * 8;
        int o = smi[O_OFF + dst], deg = smi[O_OFF + dst + 1] - o;
        u64t a0 = 0ull, a1 = 0ull, a2 = 0ull, a3 = 0ull;
        for (int i = 0; i < deg; i++) {
            int k = smi[O_CSR + o + i];
            float al = sm[O_AL2 + k];
            u64t pp = pk2(al, al);
            const float4* hr = (const float4*)&sm[O_H2 + smi[O_SRC + k]*H2S + cc];
            float4 v0 = hr[0], v1 = hr[1];
            fma2(a0, pp, pk2(v0.x, v0.y));
            fma2(a1, pp, pk2(v0.z, v0.w));
            fma2(a2, pp, pk2(v1.x, v1.y));
            fma2(a3, pp, pk2(v1.z, v1.w));
        }
        const float4* bb = (const float4*)(b2 + cc);
        float4 b0 = bb[0], b1v = bb[1], r0, r1;
        float2 f0 = up2(a0), f1 = up2(a1), f2 = up2(a2), f3 = up2(a3);
        r0.x = eluf_(f0.x + b0.x); r0.y = eluf_(f0.y + b0.y);
        r0.z = eluf_(f1.x + b0.z); r0.w = eluf_(f1.y + b0.w);
        r1.x = eluf_(f2.x + b1v.x); r1.y = eluf_(f2.y + b1v.y);
        r1.z = eluf_(f3.x + b1v.z); r1.w = eluf_(f3.y + b1v.w);
        float4* g = (float4*)&sm[O_G2 + dst*H2S + cc];
        g[0] = r0; g[1] = r1;
    }
    __syncthreads();

    // ---------------- Phase 7: LayerNorm + transpose -> hlnT[t][n]
    if (tid < NN) {
        const float4* r4 = (const float4*)&sm[O_G2 + tid*H2S];
        float4 row[16];
        float mu = 0.f;
        #pragma unroll
        for (int kk = 0; kk < 16; kk++) {
            row[kk] = r4[kk];
            mu += (row[kk].x + row[kk].y) + (row[kk].z + row[kk].w);
        }
        mu *= (1.f/HID);
        float var = 0.f;
        #pragma unroll
        for (int kk = 0; kk < 16; kk++) {
            float dx = row[kk].x-mu, dy = row[kk].y-mu, dz = row[kk].z-mu, dw = row[kk].w-mu;
            var += fmaf(dx,dx, dy*dy) + fmaf(dz,dz, dw*dw);
        }
        var *= (1.f/HID);
        float is = rsqrtf(var + 1e-5f);
        #pragma unroll
        for (int kk = 0; kk < 16; kk++) {
            int t = kk*4;
            sm[O_HLNT + (t+0)*HLNTS + tid] = (row[kk].x - mu)*is*gamma[t+0] + beta[t+0];
            sm[O_HLNT + (t+1)*HLNTS + tid] = (row[kk].y - mu)*is*gamma[t+1] + beta[t+1];
            sm[O_HLNT + (t+2)*HLNTS + tid] = (row[kk].z - mu)*is*gamma[t+2] + beta[t+2];
            sm[O_HLNT + (t+3)*HLNTS + tid] = (row[kk].w - mu)*is*gamma[t+3] + beta[t+3];
        }
    }
    __syncthreads();

    // ---------------- Phase 8: xi1[t][j] = bi1[j] + Wi1[j] . hlnT[t]  (packed dot32)
    for (int o = tid; o < HID*192; o += NTH) {
        int j = o >> 6, t = o & 63;
        const float4* wr = (const float4*)(Wi1 + j*NN);
        const float4* hr = (const float4*)&sm[O_HLNT + t*HLNTS];
        u64t a0 = 0ull, a1 = 0ull;
        #pragma unroll
        for (int kk = 0; kk < 8; kk++) {
            float4 w = wr[kk], v = hr[kk];
            fma2(a0, pk2(w.x, w.y), pk2(v.x, v.y));
            fma2(a1, pk2(w.z, w.w), pk2(v.z, v.w));
        }
        sm[O_XI + t*XIS + j] = bi1[j] + red2(a0, a1);
    }
    // Wh1 rows into registers (packed)
    u64t wh2[32]; float bh = 0.f;
    if (tid < 192) {
        bh = bh1[tid];
        const float4* w = (const float4*)(Wh1 + tid*HID);
        #pragma unroll
        for (int kk = 0; kk < 16; kk++) {
            float4 t = w[kk];
            wh2[2*kk]   = pk2(t.x, t.y);
            wh2[2*kk+1] = pk2(t.z, t.w);
        }
    }
    if (tid < HID) sm[O_HSM + tid] = 0.f;
    __syncthreads();

    // ---------------- Phase 9: GRU1 recurrence (64 steps, packed dot64)
    for (int t = 0; t < HID; t++) {
        if (tid < 192) {
            const float4* h4 = (const float4*)&sm[O_HSM];
            u64t a0 = 0ull, a1 = 0ull, a2 = 0ull, a3 = 0ull;
            #pragma unroll
            for (int kk = 0; kk < 8; kk++) {
                float4 v0 = h4[2*kk], v1 = h4[2*kk+1];
                fma2(a0, wh2[4*kk],   pk2(v0.x, v0.y));
                fma2(a1, wh2[4*kk+1], pk2(v0.z, v0.w));
                fma2(a2, wh2[4*kk+2], pk2(v1.x, v1.y));
                fma2(a3, wh2[4*kk+3], pk2(v1.z, v1.w));
            }
            sm[O_GH + tid] = bh + red2(a0, a1) + red2(a2, a3);
        }
        __syncthreads();
        if (tid < HID) {
            const float* xr = &sm[O_XI + t*XIS];
            float r  = sigmf_(xr[tid]       + sm[O_GH + tid]);
            float z  = sigmf_(xr[64 + tid]  + sm[O_GH + 64 + tid]);
            float nv = tanhf_(fmaf(r, sm[O_GH + 128 + tid], xr[128 + tid]));
            float hn = (1.f - z)*nv + z*sm[O_HSM + tid];
            sm[O_HSM + tid]        = hn;
            sm[O_YS + t*YSS + tid] = hn;
        }
        __syncthreads();
    }

    // ---------------- Phase 10: xi2[t][j] = bi2[j] + Wi2[j] . ys[t]  (packed dot64)
    for (int o = tid; o < HID*192; o += NTH) {
        int j = o >> 6, t = o & 63;
        const float4* wr = (const float4*)(Wi2 + j*HID);
        const float4* yr = (const float4*)&sm[O_YS + t*YSS];
        u64t a0 = 0ull, a1 = 0ull, a2 = 0ull, a3 = 0ull;
        #pragma unroll
        for (int kk = 0; kk < 8; kk++) {
            float4 w0 = wr[2*kk], w1 = wr[2*kk+1];
            float4 v0 = yr[2*kk], v1 = yr[2*kk+1];
            fma2(a0, pk2(w0.x, w0.y), pk2(v0.x, v0.y));
            fma2(a1, pk2(w0.z, w0.w), pk2(v0.z, v0.w));
            fma2(a2, pk2(w1.x, w1.y), pk2(v1.x, v1.y));
            fma2(a3, pk2(w1.z, w1.w), pk2(v1.z, v1.w));
        }
        sm[O_XI + t*XIS + j] = bi2[j] + red2(a0, a1) + red2(a2, a3);
    }
    if (tid < 192) {
        bh = bh2[tid];
        const float4* w = (const float4*)(Wh2 + tid*HID);
        #pragma unroll
        for (int kk = 0; kk < 16; kk++) {
            float4 t = w[kk];
            wh2[2*kk]   = pk2(t.x, t.y);
            wh2[2*kk+1] = pk2(t.z, t.w);
        }
    }
    if (tid < HID) sm[O_HSM + tid] = 0.f;
    __syncthreads();

    // ---------------- Phase 11: GRU2 recurrence (final h only)
    for (int t = 0; t < HID; t++) {
        if (tid < 192) {
            const float4* h4 = (const float4*)&sm[O_HSM];
            u64t a0 = 0ull, a1 = 0ull, a2 = 0ull, a3 = 0ull;
            #pragma unroll
            for (int kk = 0; kk < 8; kk++) {
                float4 v0 = h4[2*kk], v1 = h4[2*kk+1];
                fma2(a0, wh2[4*kk],   pk2(v0.x, v0.y));
                fma2(a1, wh2[4*kk+1], pk2(v0.z, v0.w));
                fma2(a2, wh2[4*kk+2], pk2(v1.x, v1.y));
                fma2(a3, wh2[4*kk+3], pk2(v1.z, v1.w));
            }
            sm[O_GH + tid] = bh + red2(a0, a1) + red2(a2, a3);
        }
        __syncthreads();
        if (tid < HID) {
            const float* xr = &sm[O_XI + t*XIS];
            float r  = sigmf_(xr[tid]       + sm[O_GH + tid]);
            float z  = sigmf_(xr[64 + tid]  + sm[O_GH + 64 + tid]);
            float nv = tanhf_(fmaf(r, sm[O_GH + 128 + tid], xr[128 + tid]));
            sm[O_HSM + tid] = (1.f - z)*nv + z*sm[O_HSM + tid];
        }
        __syncthreads();
    }

    // ---------------- Phase 12: final linear (packed dot64)
    if (tid < 9) {
        const float4* w = (const float4*)(Wf + tid*HID);
        const float4* h4 = (const float4*)&sm[O_HSM];
        u64t a0 = 0ull, a1 = 0ull;
        #pragma unroll
        for (int kk = 0; kk < 16; kk++) {
            float4 wv = w[kk], hv = h4[kk];
            fma2(a0, pk2(wv.x, wv.y), pk2(hv.x, hv.y));
            fma2(a1, pk2(wv.z, wv.w), pk2(hv.z, hv.w));
        }
        out[b*9 + tid] = bf[tid] + red2(a0, a1);
    }
}

extern "C" void kernel_launch(void* const* d_in, const int* in_sizes, int n_in,
                              void* d_out, int out_size) {
    (void)in_sizes; (void)n_in; (void)out_size;
    const float* x    = (const float*)d_in[0];
    const int*   ei   = (const int*)  d_in[1];
    const float* W1   = (const float*)d_in[2];
    const float* aS1  = (const float*)d_in[3];
    const float* aD1  = (const float*)d_in[4];
    const float* b1   = (const float*)d_in[5];
    const float* W2   = (const float*)d_in[6];
    const float* aS2  = (const float*)d_in[7];
    const float* aD2  = (const float*)d_in[8];
    const float* b2   = (const float*)d_in[9];
    const float* gam  = (const float*)d_in[10];
    const float* bet  = (const float*)d_in[11];
    const float* Wi1  = (const float*)d_in[12];
    const float* Wh1  = (const float*)d_in[13];
    const float* bi1  = (const float*)d_in[14];
    const float* bh1  = (const float*)d_in[15];
    const float* Wi2  = (const float*)d_in[16];
    const float* Wh2  = (const float*)d_in[17];
    const float* bi2  = (const float*)d_in[18];
    const float* bh2  = (const float*)d_in[19];
    const float* Wf   = (const float*)d_in[20];
    const float* bf   = (const float*)d_in[21];
    float* out = (float*)d_out;

    size_t smem = (size_t)SMEM_FLOATS * sizeof(float);
    cudaFuncSetAttribute(fused_gatgru_kernel,
                         cudaFuncAttributeMaxDynamicSharedMemorySize, (int)smem);
    fused_gatgru_kernel<<<512, NTH, smem>>>(
        x, ei, W1, aS1, aD1, b1, W2, aS2, aD2, b2, gam, bet,
        Wi1, Wh1, bi1, bh1, Wi2, Wh2, bi2, bh2, Wf, bf, out);
}

// round 5
// speedup vs baseline: 3.1184x; 1.0579x over previous
#include <cuda_runtime.h>
#include <math.h>

#define NN     32
#define TIN    12
#define HID    64
#define HEADS  8
#define HH     512
#define EPB    256
#define ET     288
#define E_     131072
#define NTH    256
#define RS     68
#define H2S    68
#define HLNTS  36
#define XIS    196
#define YSS    68

// shared memory offsets (floats) — same map as the 386us kernel
#define O_H1    0
#define O_XI    0
#define O_YS    12544
#define O_X     17408
#define O_ES2   17408
#define O_ED2   17440
#define O_M2    17472
#define O_IS2   17504
#define O_AL2   17536
#define O_ES    17792
#define O_E2    17824
#define O_ED    18048
#define O_E     18304
#define O_HLNT  18304
#define O_SRC   20608
#define O_DST   20896
#define O_CNT   21184
#define O_OFF   21216
#define O_SLOT  21249
#define O_CSR   21537
#define O_H2    21828
#define O_G2    24004
#define O_HSM   24004
#define O_GH    24068
#define SMEM_FLOATS 26180

typedef unsigned long long u64t;

__device__ __forceinline__ u64t pk2(float lo, float hi) {
    u64t r; asm("mov.b64 %0, {%1, %2};" : "=l"(r) : "f"(lo), "f"(hi)); return r;
}
__device__ __forceinline__ void fma2(u64t& d, u64t a, u64t b) {
    asm("fma.rn.f32x2 %0, %1, %2, %3;" : "=l"(d) : "l"(a), "l"(b), "l"(d));
}
__device__ __forceinline__ float2 up2(u64t v) {
    float2 f; asm("mov.b64 {%0, %1}, %2;" : "=f"(f.x), "=f"(f.y) : "l"(v)); return f;
}
__device__ __forceinline__ float red2(u64t a, u64t b) {
    float2 fa = up2(a), fb = up2(b);
    return (fa.x + fa.y) + (fb.x + fb.y);
}
__device__ __forceinline__ float red4(u64t a, u64t b, u64t c, u64t d) {
    float2 fa = up2(a), fb = up2(b), fc = up2(c), fd = up2(d);
    return ((fa.x + fa.y) + (fb.x + fb.y)) + ((fc.x + fc.y) + (fd.x + fd.y));
}

__device__ __forceinline__ float sigmf_(float x){ return __fdividef(1.0f, 1.0f + __expf(-x)); }
__device__ __forceinline__ float tanhf_(float x){ return 1.0f - __fdividef(2.0f, __expf(2.0f*x) + 1.0f); }
__device__ __forceinline__ float eluf_(float x){ return x>0.f ? x : (__expf(x) - 1.0f); }
__device__ __forceinline__ float lreluf_(float x){ return x>0.f ? x : 0.2f*x; }

__global__ void __launch_bounds__(NTH, 2) fused_gatgru_kernel(
    const float* __restrict__ x,   const int*   __restrict__ ei,
    const float* __restrict__ W1,  const float* __restrict__ aS1,
    const float* __restrict__ aD1, const float* __restrict__ b1,
    const float* __restrict__ W2,  const float* __restrict__ aS2,
    const float* __restrict__ aD2, const float* __restrict__ b2,
    const float* __restrict__ gamma, const float* __restrict__ beta,
    const float* __restrict__ Wi1, const float* __restrict__ Wh1,
    const float* __restrict__ bi1, const float* __restrict__ bh1,
    const float* __restrict__ Wi2, const float* __restrict__ Wh2,
    const float* __restrict__ bi2, const float* __restrict__ bh2,
    const float* __restrict__ Wf,  const float* __restrict__ bf,
    float* __restrict__ out)
{
    extern __shared__ float sm[];
    int* smi = (int*)sm;
    const int tid = threadIdx.x;
    const int b   = blockIdx.x;

    // ---------------- Phase 0
    {
        const float4* xg = (const float4*)(x + b*NN*TIN);
        float4* xs = (float4*)&sm[O_X];
        if (tid < 96) xs[tid] = xg[tid];
    }
    for (int k = tid; k < ET; k += NTH) {
        int s, d;
        if (k < EPB) { s = ei[b*EPB + k] - b*NN; d = ei[E_ + b*EPB + k] - b*NN; }
        else         { s = d = k - EPB; }
        smi[O_SRC + k] = s; smi[O_DST + k] = d;
    }
    if (tid < NN) smi[O_CNT + tid] = 0;
    __syncthreads();

    // ---------------- Phase 1: h1 = x @ W1 (packed, operands loaded as u64 pairs)
    for (int jj = 0; jj < 2; jj++) {
        int j = tid + jj*NTH;
        int h = j >> 6, c = j & 63;
        u64t wp[6];
        #pragma unroll
        for (int k = 0; k < 6; k++)
            wp[k] = pk2(W1[(2*k)*HH + j], W1[(2*k+1)*HH + j]);
        for (int n = 0; n < NN; n++) {
            const ulonglong2* xr = (const ulonglong2*)&sm[O_X + n*TIN];
            ulonglong2 x01 = xr[0];                    // x[0..3]
            u64t x2 = ((const u64t*)xr)[2];            // x[4..5]
            ulonglong2 x34 = *(const ulonglong2*)((const float*)xr + 6); // not aligned; avoid
            // safer: load remaining as u64 pairs from aligned base
            u64t a0 = 0ull, a1 = 0ull;
            fma2(a0, x01.x, wp[0]);
            fma2(a1, x01.y, wp[1]);
            fma2(a0, x2,    wp[2]);
            u64t x3 = ((const u64t*)xr)[3];            // x[6..7]
            u64t x4 = ((const u64t*)xr)[4];            // x[8..9]
            u64t x5 = ((const u64t*)xr)[5];            // x[10..11]
            fma2(a1, x3, wp[3]);
            fma2(a0, x4, wp[4]);
            fma2(a1, x5, wp[5]);
            sm[O_H1 + (n*8 + h)*RS + c] = red2(a0, a1);
        }
    }
    for (int k = tid; k < ET; k += NTH)
        smi[O_SLOT + k] = atomicAdd(&smi[O_CNT + smi[O_DST + k]], 1);
    __syncthreads();

    // ---------------- Phase 2: es/ed dots (direct u64 pair loads) + prefix sum
    {
        int n = tid >> 3, h = tid & 7;
        const ulonglong2* hr = (const ulonglong2*)&sm[O_H1 + (n*8 + h)*RS];
        const ulonglong2* as = (const ulonglong2*)(aS1 + h*HID);
        const ulonglong2* ad = (const ulonglong2*)(aD1 + h*HID);
        u64t e0 = 0ull, e1 = 0ull, d0 = 0ull, d1 = 0ull;
        #pragma unroll
        for (int kk = 0; kk < 16; kk++) {
            ulonglong2 v = hr[kk], a = as[kk], g = ad[kk];
            fma2(e0, v.x, a.x);
            fma2(e1, v.y, a.y);
            fma2(d0, v.x, g.x);
            fma2(d1, v.y, g.y);
        }
        sm[O_ES + n*8 + h] = red2(e0, e1);
        sm[O_ED + n*8 + h] = red2(d0, d1);
    }
    if (tid == 0) {
        int acc = 0;
        for (int d = 0; d < NN; d++) { smi[O_OFF + d] = acc; acc += smi[O_CNT + d]; }
        smi[O_OFF + NN] = acc;
    }
    __syncthreads();

    // ---------------- Phase 3: edge scores + CSR scatter
    for (int k = tid; k < ET; k += NTH) {
        int s = smi[O_SRC + k], d = smi[O_DST + k];
        const float4* es = (const float4*)&sm[O_ES + s*8];
        const float4* ed = (const float4*)&sm[O_ED + d*8];
        float4* eo = (float4*)&sm[O_E + k*8];
        float4 a0 = es[0], a1 = es[1], b0 = ed[0], b1 = ed[1];
        float4 r0, r1;
        r0.x = lreluf_(a0.x + b0.x); r0.y = lreluf_(a0.y + b0.y);
        r0.z = lreluf_(a0.z + b0.z); r0.w = lreluf_(a0.w + b0.w);
        r1.x = lreluf_(a1.x + b1.x); r1.y = lreluf_(a1.y + b1.y);
        r1.z = lreluf_(a1.z + b1.z); r1.w = lreluf_(a1.w + b1.w);
        eo[0] = r0; eo[1] = r1;
    }
    for (int k = tid; k < ET; k += NTH)
        smi[O_CSR + smi[O_OFF + smi[O_DST + k]] + smi[O_SLOT + k]] = k;
    __syncthreads();

    // ---------------- Phase 4: GAT1 softmax + aggregation (u64-pair accumulate)
    {
        int dst = tid >> 3, h = tid & 7;
        int o   = smi[O_OFF + dst], deg = smi[O_OFF + dst + 1] - o;
        float m = -1e30f;
        for (int i = 0; i < deg; i++)
            m = fmaxf(m, sm[O_E + smi[O_CSR + o + i]*8 + h]);
        float s = 0.f;
        for (int i = 0; i < deg; i++) {
            int k = smi[O_CSR + o + i];
            float p = __expf(sm[O_E + k*8 + h] - m);
            sm[O_E + k*8 + h] = p;
            s += p;
        }
        float inv = __fdividef(1.f, s + 1e-16f);
        u64t acc[32];
        #pragma unroll
        for (int j = 0; j < 32; j++) acc[j] = 0ull;
        for (int i = 0; i < deg; i++) {
            int k = smi[O_CSR + o + i];
            u64t pp = pk2(sm[O_E + k*8 + h], sm[O_E + k*8 + h]);
            const ulonglong2* hr = (const ulonglong2*)&sm[O_H1 + (smi[O_SRC + k]*8 + h)*RS];
            #pragma unroll
            for (int j = 0; j < 16; j++) {
                ulonglong2 v = hr[j];
                fma2(acc[2*j],   pp, v.x);
                fma2(acc[2*j+1], pp, v.y);
            }
        }
        __syncthreads();   // all h1 reads complete before in-place overwrite
        float4* orow = (float4*)&sm[O_H1 + (dst*8 + h)*RS];
        const float4* bb = (const float4*)(b1 + h*HID);
        #pragma unroll
        for (int j = 0; j < 16; j++) {
            float4 bv = bb[j], r;
            float2 lo = up2(acc[2*j]), hi = up2(acc[2*j+1]);
            r.x = eluf_(fmaf(lo.x, inv, bv.x));
            r.y = eluf_(fmaf(lo.y, inv, bv.y));
            r.z = eluf_(fmaf(hi.x, inv, bv.z));
            r.w = eluf_(fmaf(hi.y, inv, bv.w));
            orow[j] = r;
        }
    }
    __syncthreads();

    // ---------------- Phase 5: h2 = out1 @ W2 (u64-pair smem loads, packed weights)
    {
        int c = tid & 63, grp = tid >> 6;
        u64t accA[8], accB[8];
        #pragma unroll
        for (int i = 0; i < 8; i++) { accA[i] = 0ull; accB[i] = 0ull; }
        for (int hd = 0; hd < 8; hd++) {
            const float* w2p = W2 + hd*64*HID + c;
            #pragma unroll 4
            for (int kc = 0; kc < 64; kc += 4) {
                u64t wA = pk2(w2p[(kc+0)*HID], w2p[(kc+1)*HID]);
                u64t wB = pk2(w2p[(kc+2)*HID], w2p[(kc+3)*HID]);
                #pragma unroll
                for (int i = 0; i < 8; i++) {
                    ulonglong2 v = *(const ulonglong2*)&sm[O_H1 + ((grp*8+i)*8 + hd)*RS + kc];
                    fma2(accA[i], v.x, wA);
                    fma2(accB[i], v.y, wB);
                }
            }
        }
        #pragma unroll
        for (int i = 0; i < 8; i++)
            sm[O_H2 + (grp*8+i)*H2S + c] = red2(accA[i], accB[i]);
    }
    __syncthreads();

    // ---------------- Phase 6: GAT2 attention
    if (tid < 64) {
        int n = tid & 31;
        const ulonglong2* a  = (const ulonglong2*)((tid < 32) ? aS2 : aD2);
        const ulonglong2* hr = (const ulonglong2*)&sm[O_H2 + n*H2S];
        u64t a0 = 0ull, a1 = 0ull;
        #pragma unroll
        for (int kk = 0; kk < 16; kk++) {
            ulonglong2 v = hr[kk], w = a[kk];
            fma2(a0, v.x, w.x);
            fma2(a1, v.y, w.y);
        }
        sm[(tid < 32 ? O_ES2 : O_ED2) + n] = red2(a0, a1);
    }
    __syncthreads();
    for (int k = tid; k < ET; k += NTH)
        sm[O_E2 + k] = lreluf_(sm[O_ES2 + smi[O_SRC + k]] + sm[O_ED2 + smi[O_DST + k]]);
    __syncthreads();
    if (tid < NN) {
        int o = smi[O_OFF + tid], deg = smi[O_OFF + tid + 1] - o;
        float m = -1e30f;
        for (int i = 0; i < deg; i++) m = fmaxf(m, sm[O_E2 + smi[O_CSR + o + i]]);
        float s = 0.f;
        for (int i = 0; i < deg; i++) s += __expf(sm[O_E2 + smi[O_CSR + o + i]] - m);
        sm[O_M2 + tid]  = m;
        sm[O_IS2 + tid] = __fdividef(1.f, s + 1e-16f);
    }
    __syncthreads();
    for (int k = tid; k < ET; k += NTH) {
        int d = smi[O_DST + k];
        sm[O_AL2 + k] = __expf(sm[O_E2 + k] - sm[O_M2 + d]) * sm[O_IS2 + d];
    }
    __syncthreads();
    {   // aggregation + bias + elu -> g2
        int dst = tid >> 3, cc = (tid & 7) * 8;
        int o = smi[O_OFF + dst], deg = smi[O_OFF + dst + 1] - o;
        u64t a0 = 0ull, a1 = 0ull, a2 = 0ull, a3 = 0ull;
        for (int i = 0; i < deg; i++) {
            int k = smi[O_CSR + o + i];
            float al = sm[O_AL2 + k];
            u64t pp = pk2(al, al);
            const ulonglong2* hr = (const ulonglong2*)&sm[O_H2 + smi[O_SRC + k]*H2S + cc];
            ulonglong2 v0 = hr[0], v1 = hr[1];
            fma2(a0, pp, v0.x);
            fma2(a1, pp, v0.y);
            fma2(a2, pp, v1.x);
            fma2(a3, pp, v1.y);
        }
        const float4* bb = (const float4*)(b2 + cc);
        float4 b0 = bb[0], b1v = bb[1], r0, r1;
        float2 f0 = up2(a0), f1 = up2(a1), f2 = up2(a2), f3 = up2(a3);
        r0.x = eluf_(f0.x + b0.x); r0.y = eluf_(f0.y + b0.y);
        r0.z = eluf_(f1.x + b0.z); r0.w = eluf_(f1.y + b0.w);
        r1.x = eluf_(f2.x + b1v.x); r1.y = eluf_(f2.y + b1v.y);
        r1.z = eluf_(f3.x + b1v.z); r1.w = eluf_(f3.y + b1v.w);
        float4* g = (float4*)&sm[O_G2 + dst*H2S + cc];
        g[0] = r0; g[1] = r1;
    }
    __syncthreads();

    // ---------------- Phase 7: LayerNorm + transpose -> hlnT[t][n]
    if (tid < NN) {
        const float4* r4 = (const float4*)&sm[O_G2 + tid*H2S];
        float4 row[16];
        float mu = 0.f;
        #pragma unroll
        for (int kk = 0; kk < 16; kk++) {
            row[kk] = r4[kk];
            mu += (row[kk].x + row[kk].y) + (row[kk].z + row[kk].w);
        }
        mu *= (1.f/HID);
        float var = 0.f;
        #pragma unroll
        for (int kk = 0; kk < 16; kk++) {
            float dx = row[kk].x-mu, dy = row[kk].y-mu, dz = row[kk].z-mu, dw = row[kk].w-mu;
            var += fmaf(dx,dx, dy*dy) + fmaf(dz,dz, dw*dw);
        }
        var *= (1.f/HID);
        float is = rsqrtf(var + 1e-5f);
        #pragma unroll
        for (int kk = 0; kk < 16; kk++) {
            int t = kk*4;
            sm[O_HLNT + (t+0)*HLNTS + tid] = (row[kk].x - mu)*is*gamma[t+0] + beta[t+0];
            sm[O_HLNT + (t+1)*HLNTS + tid] = (row[kk].y - mu)*is*gamma[t+1] + beta[t+1];
            sm[O_HLNT + (t+2)*HLNTS + tid] = (row[kk].z - mu)*is*gamma[t+2] + beta[t+2];
            sm[O_HLNT + (t+3)*HLNTS + tid] = (row[kk].w - mu)*is*gamma[t+3] + beta[t+3];
        }
    }
    __syncthreads();

    // ---------------- Phase 8: xi1[t][j] = bi1[j] + Wi1[j] . hlnT[t]
    for (int o = tid; o < HID*192; o += NTH) {
        int j = o >> 6, t = o & 63;
        const ulonglong2* wr = (const ulonglong2*)(Wi1 + j*NN);
        const ulonglong2* hr = (const ulonglong2*)&sm[O_HLNT + t*HLNTS];
        u64t a0 = 0ull, a1 = 0ull;
        #pragma unroll
        for (int kk = 0; kk < 8; kk++) {
            ulonglong2 w = wr[kk], v = hr[kk];
            fma2(a0, w.x, v.x);
            fma2(a1, w.y, v.y);
        }
        sm[O_XI + t*XIS + j] = bi1[j] + red2(a0, a1);
    }
    // Wh1 rows into registers (packed, direct pair loads)
    u64t wh2[32]; float bh = 0.f;
    if (tid < 192) {
        bh = bh1[tid];
        const ulonglong2* w = (const ulonglong2*)(Wh1 + tid*HID);
        #pragma unroll
        for (int kk = 0; kk < 16; kk++) {
            ulonglong2 t = w[kk];
            wh2[2*kk]   = t.x;
            wh2[2*kk+1] = t.y;
        }
    }
    if (tid < HID) sm[O_HSM + tid] = 0.f;
    __syncthreads();

    // ---------------- Phase 9: GRU1 recurrence (64 steps, packed dot64)
    for (int t = 0; t < HID; t++) {
        if (tid < 192) {
            const ulonglong2* h4 = (const ulonglong2*)&sm[O_HSM];
            u64t a0 = 0ull, a1 = 0ull, a2 = 0ull, a3 = 0ull;
            #pragma unroll
            for (int kk = 0; kk < 8; kk++) {
                ulonglong2 v0 = h4[2*kk], v1 = h4[2*kk+1];
                fma2(a0, wh2[4*kk],   v0.x);
                fma2(a1, wh2[4*kk+1], v0.y);
                fma2(a2, wh2[4*kk+2], v1.x);
                fma2(a3, wh2[4*kk+3], v1.y);
            }
            sm[O_GH + tid] = bh + red4(a0, a1, a2, a3);
        }
        __syncthreads();
        if (tid < HID) {
            const float* xr = &sm[O_XI + t*XIS];
            float r  = sigmf_(xr[tid]       + sm[O_GH + tid]);
            float z  = sigmf_(xr[64 + tid]  + sm[O_GH + 64 + tid]);
            float nv = tanhf_(fmaf(r, sm[O_GH + 128 + tid], xr[128 + tid]));
            float hn = (1.f - z)*nv + z*sm[O_HSM + tid];
            sm[O_HSM + tid]        = hn;
            sm[O_YS + t*YSS + tid] = hn;
        }
        __syncthreads();
    }

    // ---------------- Phase 10: xi2[t][j] = bi2[j] + Wi2[j] . ys[t]
    for (int o = tid; o < HID*192; o += NTH) {
        int j = o >> 6, t = o & 63;
        const ulonglong2* wr = (const ulonglong2*)(Wi2 + j*HID);
        const ulonglong2* yr = (const ulonglong2*)&sm[O_YS + t*YSS];
        u64t a0 = 0ull, a1 = 0ull, a2 = 0ull, a3 = 0ull;
        #pragma unroll
        for (int kk = 0; kk < 8; kk++) {
            ulonglong2 w0 = wr[2*kk], w1 = wr[2*kk+1];
            ulonglong2 v0 = yr[2*kk], v1 = yr[2*kk+1];
            fma2(a0, w0.x, v0.x);
            fma2(a1, w0.y, v0.y);
            fma2(a2, w1.x, v1.x);
            fma2(a3, w1.y, v1.y);
        }
        sm[O_XI + t*XIS + j] = bi2[j] + red4(a0, a1, a2, a3);
    }
    if (tid < 192) {
        bh = bh2[tid];
        const ulonglong2* w = (const ulonglong2*)(Wh2 + tid*HID);
        #pragma unroll
        for (int kk = 0; kk < 16; kk++) {
            ulonglong2 t = w[kk];
            wh2[2*kk]   = t.x;
            wh2[2*kk+1] = t.y;
        }
    }
    if (tid < HID) sm[O_HSM + tid] = 0.f;
    __syncthreads();

    // ---------------- Phase 11: GRU2 recurrence (final h only)
    for (int t = 0; t < HID; t++) {
        if (tid < 192) {
            const ulonglong2* h4 = (const ulonglong2*)&sm[O_HSM];
            u64t a0 = 0ull, a1 = 0ull, a2 = 0ull, a3 = 0ull;
            #pragma unroll
            for (int kk = 0; kk < 8; kk++) {
                ulonglong2 v0 = h4[2*kk], v1 = h4[2*kk+1];
                fma2(a0, wh2[4*kk],   v0.x);
                fma2(a1, wh2[4*kk+1], v0.y);
                fma2(a2, wh2[4*kk+2], v1.x);
                fma2(a3, wh2[4*kk+3], v1.y);
            }
            sm[O_GH + tid] = bh + red4(a0, a1, a2, a3);
        }
        __syncthreads();
        if (tid < HID) {
            const float* xr = &sm[O_XI + t*XIS];
            float r  = sigmf_(xr[tid]       + sm[O_GH + tid]);
            float z  = sigmf_(xr[64 + tid]  + sm[O_GH + 64 + tid]);
            float nv = tanhf_(fmaf(r, sm[O_GH + 128 + tid], xr[128 + tid]));
            sm[O_HSM + tid] = (1.f - z)*nv + z*sm[O_HSM + tid];
        }
        __syncthreads();
    }

    // ---------------- Phase 12: final linear
    if (tid < 9) {
        const ulonglong2* w = (const ulonglong2*)(Wf + tid*HID);
        const ulonglong2* h4 = (const ulonglong2*)&sm[O_HSM];
        u64t a0 = 0ull, a1 = 0ull;
        #pragma unroll
        for (int kk = 0; kk < 16; kk++) {
            ulonglong2 wv = w[kk], hv = h4[kk];
            fma2(a0, wv.x, hv.x);
            fma2(a1, wv.y, hv.y);
        }
        out[b*9 + tid] = bf[tid] + red2(a0, a1);
    }
}

extern "C" void kernel_launch(void* const* d_in, const int* in_sizes, int n_in,
                              void* d_out, int out_size) {
    (void)in_sizes; (void)n_in; (void)out_size;
    const float* x    = (const float*)d_in[0];
    const int*   ei   = (const int*)  d_in[1];
    const float* W1   = (const float*)d_in[2];
    const float* aS1  = (const float*)d_in[3];
    const float* aD1  = (const float*)d_in[4];
    const float* b1   = (const float*)d_in[5];
    const float* W2   = (const float*)d_in[6];
    const float* aS2  = (const float*)d_in[7];
    const float* aD2  = (const float*)d_in[8];
    const float* b2   = (const float*)d_in[9];
    const float* gam  = (const float*)d_in[10];
    const float* bet  = (const float*)d_in[11];
    const float* Wi1  = (const float*)d_in[12];
    const float* Wh1  = (const float*)d_in[13];
    const float* bi1  = (const float*)d_in[14];
    const float* bh1  = (const float*)d_in[15];
    const float* Wi2  = (const float*)d_in[16];
    const float* Wh2  = (const float*)d_in[17];
    const float* bi2  = (const float*)d_in[18];
    const float* bh2  = (const float*)d_in[19];
    const float* Wf   = (const float*)d_in[20];
    const float* bf   = (const float*)d_in[21];
    float* out = (float*)d_out;

    size_t smem = (size_t)SMEM_FLOATS * sizeof(float);
    cudaFuncSetAttribute(fused_gatgru_kernel,
                         cudaFuncAttributeMaxDynamicSharedMemorySize, (int)smem);
    fused_gatgru_kernel<<<512, NTH, smem>>>(
        x, ei, W1, aS1, aD1, b1, W2, aS2, aD2, b2, gam, bet,
        Wi1, Wh1, bi1, bh1, Wi2, Wh2, bi2, bh2, Wf, bf, out);
}

// round 6
// speedup vs baseline: 3.6493x; 1.1703x over previous
#include <cuda_runtime.h>
#include <math.h>

#define NN     32
#define TIN    12
#define HID    64
#define HEADS  8
#define HH     512
#define EPB    256
#define ET     288
#define E_     131072
#define NTH    256
#define RS     68
#define H2S    68
#define HLNTS  36
#define XIS    196
#define YSS    68

// shared memory offsets (floats) — same map as the 365us kernel
#define O_H1    0
#define O_XI    0
#define O_YS    12544
#define O_X     17408
#define O_ES2   17408
#define O_ED2   17440
#define O_M2    17472
#define O_IS2   17504
#define O_AL2   17536
#define O_ES    17792
#define O_E2    17824
#define O_ED    18048
#define O_E     18304
#define O_HLNT  18304
#define O_SRC   20608
#define O_DST   20896
#define O_CNT   21184
#define O_OFF   21216
#define O_SLOT  21249
#define O_CSR   21537
#define O_H2    21828
#define O_G2    24004
#define O_HSM   24004
#define O_GH    24068
#define SMEM_FLOATS 26180

typedef unsigned long long u64t;

__device__ __forceinline__ u64t pk2(float lo, float hi) {
    u64t r; asm("mov.b64 %0, {%1, %2};" : "=l"(r) : "f"(lo), "f"(hi)); return r;
}
__device__ __forceinline__ void fma2(u64t& d, u64t a, u64t b) {
    asm("fma.rn.f32x2 %0, %1, %2, %3;" : "=l"(d) : "l"(a), "l"(b), "l"(d));
}
__device__ __forceinline__ float2 up2(u64t v) {
    float2 f; asm("mov.b64 {%0, %1}, %2;" : "=f"(f.x), "=f"(f.y) : "l"(v)); return f;
}
__device__ __forceinline__ float red2(u64t a, u64t b) {
    float2 fa = up2(a), fb = up2(b);
    return (fa.x + fa.y) + (fb.x + fb.y);
}
__device__ __forceinline__ float red4(u64t a, u64t b, u64t c, u64t d) {
    float2 fa = up2(a), fb = up2(b), fc = up2(c), fd = up2(d);
    return ((fa.x + fa.y) + (fb.x + fb.y)) + ((fc.x + fc.y) + (fd.x + fd.y));
}

__device__ __forceinline__ float sigmf_(float x){ return __fdividef(1.0f, 1.0f + __expf(-x)); }
__device__ __forceinline__ float tanhf_(float x){ return 1.0f - __fdividef(2.0f, __expf(2.0f*x) + 1.0f); }
__device__ __forceinline__ float eluf_(float x){ return x>0.f ? x : (__expf(x) - 1.0f); }
__device__ __forceinline__ float lreluf_(float x){ return x>0.f ? x : 0.2f*x; }

__global__ void __launch_bounds__(NTH, 2) fused_gatgru_kernel(
    const float* __restrict__ x,   const int*   __restrict__ ei,
    const float* __restrict__ W1,  const float* __restrict__ aS1,
    const float* __restrict__ aD1, const float* __restrict__ b1,
    const float* __restrict__ W2,  const float* __restrict__ aS2,
    const float* __restrict__ aD2, const float* __restrict__ b2,
    const float* __restrict__ gamma, const float* __restrict__ beta,
    const float* __restrict__ Wi1, const float* __restrict__ Wh1,
    const float* __restrict__ bi1, const float* __restrict__ bh1,
    const float* __restrict__ Wi2, const float* __restrict__ Wh2,
    const float* __restrict__ bi2, const float* __restrict__ bh2,
    const float* __restrict__ Wf,  const float* __restrict__ bf,
    float* __restrict__ out)
{
    extern __shared__ float sm[];
    int* smi = (int*)sm;
    const int tid = threadIdx.x;
    const int b   = blockIdx.x;

    // ---------------- Phase 0
    {
        const float4* xg = (const float4*)(x + b*NN*TIN);
        float4* xs = (float4*)&sm[O_X];
        if (tid < 96) xs[tid] = xg[tid];
    }
    for (int k = tid; k < ET; k += NTH) {
        int s, d;
        if (k < EPB) { s = ei[b*EPB + k] - b*NN; d = ei[E_ + b*EPB + k] - b*NN; }
        else         { s = d = k - EPB; }
        smi[O_SRC + k] = s; smi[O_DST + k] = d;
    }
    if (tid < NN) smi[O_CNT + tid] = 0;
    __syncthreads();

    // ---------------- Phase 1: h1 = x @ W1 (packed)
    for (int jj = 0; jj < 2; jj++) {
        int j = tid + jj*NTH;
        int h = j >> 6, c = j & 63;
        u64t wp[6];
        #pragma unroll
        for (int k = 0; k < 6; k++)
            wp[k] = pk2(W1[(2*k)*HH + j], W1[(2*k+1)*HH + j]);
        for (int n = 0; n < NN; n++) {
            const u64t* xr = (const u64t*)&sm[O_X + n*TIN];
            u64t a0 = 0ull, a1 = 0ull;
            fma2(a0, xr[0], wp[0]);
            fma2(a1, xr[1], wp[1]);
            fma2(a0, xr[2], wp[2]);
            fma2(a1, xr[3], wp[3]);
            fma2(a0, xr[4], wp[4]);
            fma2(a1, xr[5], wp[5]);
            sm[O_H1 + (n*8 + h)*RS + c] = red2(a0, a1);
        }
    }
    for (int k = tid; k < ET; k += NTH)
        smi[O_SLOT + k] = atomicAdd(&smi[O_CNT + smi[O_DST + k]], 1);
    __syncthreads();

    // ---------------- Phase 2: es/ed dots + prefix sum
    {
        int n = tid >> 3, h = tid & 7;
        const ulonglong2* hr = (const ulonglong2*)&sm[O_H1 + (n*8 + h)*RS];
        const ulonglong2* as = (const ulonglong2*)(aS1 + h*HID);
        const ulonglong2* ad = (const ulonglong2*)(aD1 + h*HID);
        u64t e0 = 0ull, e1 = 0ull, d0 = 0ull, d1 = 0ull;
        #pragma unroll
        for (int kk = 0; kk < 16; kk++) {
            ulonglong2 v = hr[kk], a = as[kk], g = ad[kk];
            fma2(e0, v.x, a.x);
            fma2(e1, v.y, a.y);
            fma2(d0, v.x, g.x);
            fma2(d1, v.y, g.y);
        }
        sm[O_ES + n*8 + h] = red2(e0, e1);
        sm[O_ED + n*8 + h] = red2(d0, d1);
    }
    if (tid == 0) {
        int acc = 0;
        for (int d = 0; d < NN; d++) { smi[O_OFF + d] = acc; acc += smi[O_CNT + d]; }
        smi[O_OFF + NN] = acc;
    }
    __syncthreads();

    // ---------------- Phase 3: edge scores + CSR scatter
    for (int k = tid; k < ET; k += NTH) {
        int s = smi[O_SRC + k], d = smi[O_DST + k];
        const float4* es = (const float4*)&sm[O_ES + s*8];
        const float4* ed = (const float4*)&sm[O_ED + d*8];
        float4* eo = (float4*)&sm[O_E + k*8];
        float4 a0 = es[0], a1 = es[1], b0 = ed[0], b1 = ed[1];
        float4 r0, r1;
        r0.x = lreluf_(a0.x + b0.x); r0.y = lreluf_(a0.y + b0.y);
        r0.z = lreluf_(a0.z + b0.z); r0.w = lreluf_(a0.w + b0.w);
        r1.x = lreluf_(a1.x + b1.x); r1.y = lreluf_(a1.y + b1.y);
        r1.z = lreluf_(a1.z + b1.z); r1.w = lreluf_(a1.w + b1.w);
        eo[0] = r0; eo[1] = r1;
    }
    for (int k = tid; k < ET; k += NTH)
        smi[O_CSR + smi[O_OFF + smi[O_DST + k]] + smi[O_SLOT + k]] = k;
    __syncthreads();

    // ---------------- Phase 4: GAT1 softmax + aggregation
    {
        int dst = tid >> 3, h = tid & 7;
        int o   = smi[O_OFF + dst], deg = smi[O_OFF + dst + 1] - o;
        float m = -1e30f;
        for (int i = 0; i < deg; i++)
            m = fmaxf(m, sm[O_E + smi[O_CSR + o + i]*8 + h]);
        float s = 0.f;
        for (int i = 0; i < deg; i++) {
            int k = smi[O_CSR + o + i];
            float p = __expf(sm[O_E + k*8 + h] - m);
            sm[O_E + k*8 + h] = p;
            s += p;
        }
        float inv = __fdividef(1.f, s + 1e-16f);
        u64t acc[32];
        #pragma unroll
        for (int j = 0; j < 32; j++) acc[j] = 0ull;
        for (int i = 0; i < deg; i++) {
            int k = smi[O_CSR + o + i];
            u64t pp = pk2(sm[O_E + k*8 + h], sm[O_E + k*8 + h]);
            const ulonglong2* hr = (const ulonglong2*)&sm[O_H1 + (smi[O_SRC + k]*8 + h)*RS];
            #pragma unroll
            for (int j = 0; j < 16; j++) {
                ulonglong2 v = hr[j];
                fma2(acc[2*j],   pp, v.x);
                fma2(acc[2*j+1], pp, v.y);
            }
        }
        __syncthreads();
        float4* orow = (float4*)&sm[O_H1 + (dst*8 + h)*RS];
        const float4* bb = (const float4*)(b1 + h*HID);
        #pragma unroll
        for (int j = 0; j < 16; j++) {
            float4 bv = bb[j], r;
            float2 lo = up2(acc[2*j]), hi = up2(acc[2*j+1]);
            r.x = eluf_(fmaf(lo.x, inv, bv.x));
            r.y = eluf_(fmaf(lo.y, inv, bv.y));
            r.z = eluf_(fmaf(hi.x, inv, bv.z));
            r.w = eluf_(fmaf(hi.y, inv, bv.w));
            orow[j] = r;
        }
    }
    __syncthreads();

    // ---------------- Phase 5: h2 = out1 @ W2
    {
        int c = tid & 63, grp = tid >> 6;
        u64t accA[8], accB[8];
        #pragma unroll
        for (int i = 0; i < 8; i++) { accA[i] = 0ull; accB[i] = 0ull; }
        for (int hd = 0; hd < 8; hd++) {
            const float* w2p = W2 + hd*64*HID + c;
            #pragma unroll 4
            for (int kc = 0; kc < 64; kc += 4) {
                u64t wA = pk2(w2p[(kc+0)*HID], w2p[(kc+1)*HID]);
                u64t wB = pk2(w2p[(kc+2)*HID], w2p[(kc+3)*HID]);
                #pragma unroll
                for (int i = 0; i < 8; i++) {
                    ulonglong2 v = *(const ulonglong2*)&sm[O_H1 + ((grp*8+i)*8 + hd)*RS + kc];
                    fma2(accA[i], v.x, wA);
                    fma2(accB[i], v.y, wB);
                }
            }
        }
        #pragma unroll
        for (int i = 0; i < 8; i++)
            sm[O_H2 + (grp*8+i)*H2S + c] = red2(accA[i], accB[i]);
    }
    __syncthreads();

    // ---------------- Phase 6: GAT2 attention
    if (tid < 64) {
        int n = tid & 31;
        const ulonglong2* a  = (const ulonglong2*)((tid < 32) ? aS2 : aD2);
        const ulonglong2* hr = (const ulonglong2*)&sm[O_H2 + n*H2S];
        u64t a0 = 0ull, a1 = 0ull;
        #pragma unroll
        for (int kk = 0; kk < 16; kk++) {
            ulonglong2 v = hr[kk], w = a[kk];
            fma2(a0, v.x, w.x);
            fma2(a1, v.y, w.y);
        }
        sm[(tid < 32 ? O_ES2 : O_ED2) + n] = red2(a0, a1);
    }
    __syncthreads();
    for (int k = tid; k < ET; k += NTH)
        sm[O_E2 + k] = lreluf_(sm[O_ES2 + smi[O_SRC + k]] + sm[O_ED2 + smi[O_DST + k]]);
    __syncthreads();
    if (tid < NN) {
        int o = smi[O_OFF + tid], deg = smi[O_OFF + tid + 1] - o;
        float m = -1e30f;
        for (int i = 0; i < deg; i++) m = fmaxf(m, sm[O_E2 + smi[O_CSR + o + i]]);
        float s = 0.f;
        for (int i = 0; i < deg; i++) s += __expf(sm[O_E2 + smi[O_CSR + o + i]] - m);
        sm[O_M2 + tid]  = m;
        sm[O_IS2 + tid] = __fdividef(1.f, s + 1e-16f);
    }
    __syncthreads();
    for (int k = tid; k < ET; k += NTH) {
        int d = smi[O_DST + k];
        sm[O_AL2 + k] = __expf(sm[O_E2 + k] - sm[O_M2 + d]) * sm[O_IS2 + d];
    }
    __syncthreads();
    {
        int dst = tid >> 3, cc = (tid & 7) * 8;
        int o = smi[O_OFF + dst], deg = smi[O_OFF + dst + 1] - o;
        u64t a0 = 0ull, a1 = 0ull, a2 = 0ull, a3 = 0ull;
        for (int i = 0; i < deg; i++) {
            int k = smi[O_CSR + o + i];
            float al = sm[O_AL2 + k];
            u64t pp = pk2(al, al);
            const ulonglong2* hr = (const ulonglong2*)&sm[O_H2 + smi[O_SRC + k]*H2S + cc];
            ulonglong2 v0 = hr[0], v1 = hr[1];
            fma2(a0, pp, v0.x);
            fma2(a1, pp, v0.y);
            fma2(a2, pp, v1.x);
            fma2(a3, pp, v1.y);
        }
        const float4* bb = (const float4*)(b2 + cc);
        float4 b0 = bb[0], b1v = bb[1], r0, r1;
        float2 f0 = up2(a0), f1 = up2(a1), f2 = up2(a2), f3 = up2(a3);
        r0.x = eluf_(f0.x + b0.x); r0.y = eluf_(f0.y + b0.y);
        r0.z = eluf_(f1.x + b0.z); r0.w = eluf_(f1.y + b0.w);
        r1.x = eluf_(f2.x + b1v.x); r1.y = eluf_(f2.y + b1v.y);
        r1.z = eluf_(f3.x + b1v.z); r1.w = eluf_(f3.y + b1v.w);
        float4* g = (float4*)&sm[O_G2 + dst*H2S + cc];
        g[0] = r0; g[1] = r1;
    }
    __syncthreads();

    // ---------------- Phase 7: LayerNorm + transpose -> hlnT[t][n]
    if (tid < NN) {
        const float4* r4 = (const float4*)&sm[O_G2 + tid*H2S];
        float4 row[16];
        float mu = 0.f;
        #pragma unroll
        for (int kk = 0; kk < 16; kk++) {
            row[kk] = r4[kk];
            mu += (row[kk].x + row[kk].y) + (row[kk].z + row[kk].w);
        }
        mu *= (1.f/HID);
        float var = 0.f;
        #pragma unroll
        for (int kk = 0; kk < 16; kk++) {
            float dx = row[kk].x-mu, dy = row[kk].y-mu, dz = row[kk].z-mu, dw = row[kk].w-mu;
            var += fmaf(dx,dx, dy*dy) + fmaf(dz,dz, dw*dw);
        }
        var *= (1.f/HID);
        float is = rsqrtf(var + 1e-5f);
        #pragma unroll
        for (int kk = 0; kk < 16; kk++) {
            int t = kk*4;
            sm[O_HLNT + (t+0)*HLNTS + tid] = (row[kk].x - mu)*is*gamma[t+0] + beta[t+0];
            sm[O_HLNT + (t+1)*HLNTS + tid] = (row[kk].y - mu)*is*gamma[t+1] + beta[t+1];
            sm[O_HLNT + (t+2)*HLNTS + tid] = (row[kk].z - mu)*is*gamma[t+2] + beta[t+2];
            sm[O_HLNT + (t+3)*HLNTS + tid] = (row[kk].w - mu)*is*gamma[t+3] + beta[t+3];
        }
    }
    __syncthreads();

    // ---------------- Phase 8: xi1 = hlnT @ Wi1^T + bi1  (warp-tiled 16j x 32t)
    {
        const int wid = tid >> 5, lane = tid & 31;
        for (int tile = wid; tile < 24; tile += 8) {
            int j0 = (tile >> 1) * 16;
            int t  = (tile & 1) * 32 + lane;
            u64t acc[16];
            #pragma unroll
            for (int q = 0; q < 16; q++) acc[q] = 0ull;
            const float* hrow = &sm[O_HLNT + t*HLNTS];
            #pragma unroll
            for (int kc = 0; kc < NN; kc += 4) {
                ulonglong2 hv = *(const ulonglong2*)&hrow[kc];
                #pragma unroll
                for (int q = 0; q < 16; q++) {
                    ulonglong2 wv = *(const ulonglong2*)&Wi1[(j0+q)*NN + kc];
                    fma2(acc[q], wv.x, hv.x);
                    fma2(acc[q], wv.y, hv.y);
                }
            }
            float* xo = &sm[O_XI + t*XIS + j0];
            #pragma unroll
            for (int q = 0; q < 16; q++) {
                float2 f = up2(acc[q]);
                xo[q] = bi1[j0+q] + (f.x + f.y);
            }
        }
    }
    // Wh1 rows into registers
    u64t wh2[32]; float bh = 0.f;
    if (tid < 192) {
        bh = bh1[tid];
        const ulonglong2* w = (const ulonglong2*)(Wh1 + tid*HID);
        #pragma unroll
        for (int kk = 0; kk < 16; kk++) {
            ulonglong2 t = w[kk];
            wh2[2*kk]   = t.x;
            wh2[2*kk+1] = t.y;
        }
    }
    if (tid < HID) sm[O_HSM + tid] = 0.f;
    __syncthreads();

    // ---------------- Phase 9: GRU1 recurrence (64 steps), store ys
    for (int t = 0; t < HID; t++) {
        if (tid < 192) {
            const ulonglong2* h4 = (const ulonglong2*)&sm[O_HSM];
            u64t a0 = 0ull, a1 = 0ull, a2 = 0ull, a3 = 0ull;
            #pragma unroll
            for (int kk = 0; kk < 8; kk++) {
                ulonglong2 v0 = h4[2*kk], v1 = h4[2*kk+1];
                fma2(a0, wh2[4*kk],   v0.x);
                fma2(a1, wh2[4*kk+1], v0.y);
                fma2(a2, wh2[4*kk+2], v1.x);
                fma2(a3, wh2[4*kk+3], v1.y);
            }
            sm[O_GH + tid] = bh + red4(a0, a1, a2, a3);
        }
        __syncthreads();
        if (tid < HID) {
            const float* xr = &sm[O_XI + t*XIS];
            float r  = sigmf_(xr[tid]       + sm[O_GH + tid]);
            float z  = sigmf_(xr[64 + tid]  + sm[O_GH + 64 + tid]);
            float nv = tanhf_(fmaf(r, sm[O_GH + 128 + tid], xr[128 + tid]));
            float hn = (1.f - z)*nv + z*sm[O_HSM + tid];
            sm[O_HSM + tid]        = hn;
            sm[O_YS + t*YSS + tid] = hn;
        }
        __syncthreads();
    }

    // ---------------- Phase 10: xi2 = ys @ Wi2^T + bi2  (warp-tiled 16j x 32t)
    {
        const int wid = tid >> 5, lane = tid & 31;
        for (int tile = wid; tile < 24; tile += 8) {
            int j0 = (tile >> 1) * 16;
            int t  = (tile & 1) * 32 + lane;
            u64t acc[16];
            #pragma unroll
            for (int q = 0; q < 16; q++) acc[q] = 0ull;
            const float* yrow = &sm[O_YS + t*YSS];
            #pragma unroll 4
            for (int kc = 0; kc < HID; kc += 4) {
                ulonglong2 yv = *(const ulonglong2*)&yrow[kc];
                #pragma unroll
                for (int q = 0; q < 16; q++) {
                    ulonglong2 wv = *(const ulonglong2*)&Wi2[(j0+q)*HID + kc];
                    fma2(acc[q], wv.x, yv.x);
                    fma2(acc[q], wv.y, yv.y);
                }
            }
            float* xo = &sm[O_XI + t*XIS + j0];
            #pragma unroll
            for (int q = 0; q < 16; q++) {
                float2 f = up2(acc[q]);
                xo[q] = bi2[j0+q] + (f.x + f.y);
            }
        }
    }
    if (tid < 192) {
        bh = bh2[tid];
        const ulonglong2* w = (const ulonglong2*)(Wh2 + tid*HID);
        #pragma unroll
        for (int kk = 0; kk < 16; kk++) {
            ulonglong2 t = w[kk];
            wh2[2*kk]   = t.x;
            wh2[2*kk+1] = t.y;
        }
    }
    if (tid < HID) sm[O_HSM + tid] = 0.f;
    __syncthreads();

    // ---------------- Phase 11: GRU2 recurrence (final h only)
    for (int t = 0; t < HID; t++) {
        if (tid < 192) {
            const ulonglong2* h4 = (const ulonglong2*)&sm[O_HSM];
            u64t a0 = 0ull, a1 = 0ull, a2 = 0ull, a3 = 0ull;
            #pragma unroll
            for (int kk = 0; kk < 8; kk++) {
                ulonglong2 v0 = h4[2*kk], v1 = h4[2*kk+1];
                fma2(a0, wh2[4*kk],   v0.x);
                fma2(a1, wh2[4*kk+1], v0.y);
                fma2(a2, wh2[4*kk+2], v1.x);
                fma2(a3, wh2[4*kk+3], v1.y);
            }
            sm[O_GH + tid] = bh + red4(a0, a1, a2, a3);
        }
        __syncthreads();
        if (tid < HID) {
            const float* xr = &sm[O_XI + t*XIS];
            float r  = sigmf_(xr[tid]       + sm[O_GH + tid]);
            float z  = sigmf_(xr[64 + tid]  + sm[O_GH + 64 + tid]);
            float nv = tanhf_(fmaf(r, sm[O_GH + 128 + tid], xr[128 + tid]));
            sm[O_HSM + tid] = (1.f - z)*nv + z*sm[O_HSM + tid];
        }
        __syncthreads();
    }

    // ---------------- Phase 12: final linear
    if (tid < 9) {
        const ulonglong2* w = (const ulonglong2*)(Wf + tid*HID);
        const ulonglong2* h4 = (const ulonglong2*)&sm[O_HSM];
        u64t a0 = 0ull, a1 = 0ull;
        #pragma unroll
        for (int kk = 0; kk < 16; kk++) {
            ulonglong2 wv = w[kk], hv = h4[kk];
            fma2(a0, wv.x, hv.x);
            fma2(a1, wv.y, hv.y);
        }
        out[b*9 + tid] = bf[tid] + red2(a0, a1);
    }
}

extern "C" void kernel_launch(void* const* d_in, const int* in_sizes, int n_in,
                              void* d_out, int out_size) {
    (void)in_sizes; (void)n_in; (void)out_size;
    const float* x    = (const float*)d_in[0];
    const int*   ei   = (const int*)  d_in[1];
    const float* W1   = (const float*)d_in[2];
    const float* aS1  = (const float*)d_in[3];
    const float* aD1  = (const float*)d_in[4];
    const float* b1   = (const float*)d_in[5];
    const float* W2   = (const float*)d_in[6];
    const float* aS2  = (const float*)d_in[7];
    const float* aD2  = (const float*)d_in[8];
    const float* b2   = (const float*)d_in[9];
    const float* gam  = (const float*)d_in[10];
    const float* bet  = (const float*)d_in[11];
    const float* Wi1  = (const float*)d_in[12];
    const float* Wh1  = (const float*)d_in[13];
    const float* bi1  = (const float*)d_in[14];
    const float* bh1  = (const float*)d_in[15];
    const float* Wi2  = (const float*)d_in[16];
    const float* Wh2  = (const float*)d_in[17];
    const float* bi2  = (const float*)d_in[18];
    const float* bh2  = (const float*)d_in[19];
    const float* Wf   = (const float*)d_in[20];
    const float* bf   = (const float*)d_in[21];
    float* out = (float*)d_out;

    size_t smem = (size_t)SMEM_FLOATS * sizeof(float);
    cudaFuncSetAttribute(fused_gatgru_kernel,
                         cudaFuncAttributeMaxDynamicSharedMemorySize, (int)smem);
    fused_gatgru_kernel<<<512, NTH, smem>>>(
        x, ei, W1, aS1, aD1, b1, W2, aS2, aD2, b2, gam, bet,
        Wi1, Wh1, bi1, bh1, Wi2, Wh2, bi2, bh2, Wf, bf, out);
}